// round 2
// baseline (speedup 1.0000x reference)
#include <cuda_runtime.h>
#include <math.h>

#define NQBITS 10
#define SDIM   1024
#define NL     32
#define NB     128
#define NPQ    40

// ---------------------------------------------------------------------------
// scratch: cos/sin of theta/2 per (b, l, gate)
// ---------------------------------------------------------------------------
__device__ float g_cs[NB * NL * NPQ * 2];

// ---------------------------------------------------------------------------
// gate tables (compile-time).  bit position = 9 - wire.
// type: 0 = RY (PA = bit pos of wire), 1 = CRX (PA = control bit pos, PB = target bit pos)
// ---------------------------------------------------------------------------
constexpr int G_TYPE[40] = {0,0,0,0,0,0,0,0,0,0, 1,1,1,1,1,1,1,1,1,1,
                            0,0,0,0,0,0,0,0,0,0, 1,1,1,1,1,1,1,1,1,1};
constexpr int G_PA[40]   = {9,8,7,6,5,4,3,2,1,0, 0,1,2,3,4,5,6,7,8,9,
                            9,8,7,6,5,4,3,2,1,0, 0,9,8,7,6,5,4,3,2,1};
constexpr int G_PB[40]   = {0,0,0,0,0,0,0,0,0,0, 9,0,1,2,3,4,5,6,7,8,
                            0,0,0,0,0,0,0,0,0,0, 1,0,9,8,7,6,5,4,3,2};

// lane owns amps idx = r*32 + lane  (idx bits[4:0]=lane, bits[9:5]=r)
// bit position P < 5  -> lane bit P (cross-lane via shfl_xor)
// bit position P >= 5 -> register bit P-5 (within-lane pair)

// ---- RY, cross-lane pair ----
template<int LB>
__device__ __forceinline__ void ry_lane(float2 (&s)[32], float c, float sn, unsigned lane) {
    float sgn = ((lane >> LB) & 1u) ? sn : -sn;
#pragma unroll
    for (int r = 0; r < 32; ++r) {
        float px = __shfl_xor_sync(0xffffffffu, s[r].x, 1 << LB);
        float py = __shfl_xor_sync(0xffffffffu, s[r].y, 1 << LB);
        s[r].x = fmaf(sgn, px, c * s[r].x);
        s[r].y = fmaf(sgn, py, c * s[r].y);
    }
}

// ---- RY, register pair ----
template<int RB>
__device__ __forceinline__ void ry_reg(float2 (&s)[32], float c, float sn) {
#pragma unroll
    for (int r0 = 0; r0 < 32; ++r0) {
        if ((r0 >> RB) & 1) continue;          // folded at compile time
        const int r1 = r0 | (1 << RB);
        float2 a0 = s[r0], a1 = s[r1];
        s[r0].x = fmaf(-sn, a1.x, c * a0.x);
        s[r0].y = fmaf(-sn, a1.y, c * a0.y);
        s[r1].x = fmaf( sn, a0.x, c * a1.x);
        s[r1].y = fmaf( sn, a0.y, c * a1.y);
    }
}

// ---- RX (new = c*self - i*sn*partner), cross-lane; both halves symmetric ----
template<int LB>
__device__ __forceinline__ void rx_lane(float2 (&s)[32], float c, float sn) {
#pragma unroll
    for (int r = 0; r < 32; ++r) {
        float px = __shfl_xor_sync(0xffffffffu, s[r].x, 1 << LB);
        float py = __shfl_xor_sync(0xffffffffu, s[r].y, 1 << LB);
        s[r].x = fmaf( sn, py, c * s[r].x);
        s[r].y = fmaf(-sn, px, c * s[r].y);
    }
}

// ---- RX, register pair ----
template<int RB>
__device__ __forceinline__ void rx_reg(float2 (&s)[32], float c, float sn) {
#pragma unroll
    for (int r0 = 0; r0 < 32; ++r0) {
        if ((r0 >> RB) & 1) continue;
        const int r1 = r0 | (1 << RB);
        float2 a0 = s[r0], a1 = s[r1];
        s[r0].x = fmaf( sn, a1.y, c * a0.x);
        s[r0].y = fmaf(-sn, a1.x, c * a0.y);
        s[r1].x = fmaf( sn, a0.y, c * a1.x);
        s[r1].y = fmaf(-sn, a0.x, c * a1.y);
    }
}

// ---- CRX, register control + lane target: only regs with control bit = 1 ----
template<int CRB, int TLB>
__device__ __forceinline__ void crx_rl(float2 (&s)[32], float c, float sn) {
#pragma unroll
    for (int r = 0; r < 32; ++r) {
        if (!((r >> CRB) & 1)) continue;
        float px = __shfl_xor_sync(0xffffffffu, s[r].x, 1 << TLB);
        float py = __shfl_xor_sync(0xffffffffu, s[r].y, 1 << TLB);
        s[r].x = fmaf( sn, py, c * s[r].x);
        s[r].y = fmaf(-sn, px, c * s[r].y);
    }
}

// ---- CRX, register control + register target ----
template<int CRB, int TRB>
__device__ __forceinline__ void crx_rr(float2 (&s)[32], float c, float sn) {
#pragma unroll
    for (int r0 = 0; r0 < 32; ++r0) {
        if (!((r0 >> CRB) & 1)) continue;
        if ((r0 >> TRB) & 1) continue;
        const int r1 = r0 | (1 << TRB);
        float2 a0 = s[r0], a1 = s[r1];
        s[r0].x = fmaf( sn, a1.y, c * a0.x);
        s[r0].y = fmaf(-sn, a1.x, c * a0.y);
        s[r1].x = fmaf( sn, a0.y, c * a1.x);
        s[r1].y = fmaf(-sn, a0.x, c * a1.y);
    }
}

// ---- gate dispatcher ----
template<int K>
__device__ __forceinline__ void do_gate(float2 (&s)[32], const float* csl, unsigned lane) {
    const float c  = csl[2 * K];
    const float sn = csl[2 * K + 1];
    constexpr int ty = G_TYPE[K];
    constexpr int A  = G_PA[K];
    constexpr int Bp = G_PB[K];
    if constexpr (ty == 0) {
        if constexpr (A < 5) ry_lane<A>(s, c, sn, lane);
        else                 ry_reg<A - 5>(s, c, sn);
    } else {
        if constexpr (A < 5) {               // lane-bit control: identity trick
            const int cb = (lane >> A) & 1u;
            const float ce = cb ? c  : 1.0f;
            const float se = cb ? sn : 0.0f;
            if constexpr (Bp < 5) rx_lane<Bp>(s, ce, se);
            else                  rx_reg<Bp - 5>(s, ce, se);
        } else {
            if constexpr (Bp < 5) crx_rl<A - 5, Bp>(s, c, sn);
            else                  crx_rr<A - 5, Bp - 5>(s, c, sn);
        }
    }
}

template<int K = 0>
__device__ __forceinline__ void run_gates(float2 (&s)[32], const float* csl, unsigned lane) {
    if constexpr (K < 40) {
        do_gate<K>(s, csl, lane);
        run_gates<K + 1>(s, csl, lane);
    }
}

// ---- measurement of one wire (x, y, z) ----
template<int WIRE>
__device__ __forceinline__ void measure_wire(const float2 (&s)[32], unsigned lane, float* outb) {
    constexpr int P = 9 - WIRE;
    float cr = 0.f, ci = 0.f, zz = 0.f;
    if constexpr (P < 5) {
        const int bit = (lane >> P) & 1u;
        const float f0 = bit ? 0.f : 1.f;
        const float zs = bit ? -1.f : 1.f;
#pragma unroll
        for (int r = 0; r < 32; ++r) {
            float px = __shfl_xor_sync(0xffffffffu, s[r].x, 1 << P);
            float py = __shfl_xor_sync(0xffffffffu, s[r].y, 1 << P);
            cr += f0 * (s[r].x * px + s[r].y * py);
            ci += f0 * (s[r].x * py - s[r].y * px);
            zz += zs * (s[r].x * s[r].x + s[r].y * s[r].y);
        }
    } else {
        constexpr int RB = P - 5;
#pragma unroll
        for (int r0 = 0; r0 < 32; ++r0) {
            if ((r0 >> RB) & 1) continue;
            const int r1 = r0 | (1 << RB);
            float2 a0 = s[r0], a1 = s[r1];
            cr += a0.x * a1.x + a0.y * a1.y;
            ci += a0.x * a1.y - a0.y * a1.x;
            zz += (a0.x * a0.x + a0.y * a0.y) - (a1.x * a1.x + a1.y * a1.y);
        }
    }
#pragma unroll
    for (int m = 16; m; m >>= 1) {
        cr += __shfl_xor_sync(0xffffffffu, cr, m);
        ci += __shfl_xor_sync(0xffffffffu, ci, m);
        zz += __shfl_xor_sync(0xffffffffu, zz, m);
    }
    if (lane == 0) {
        outb[WIRE]      = 2.0f * cr;
        outb[10 + WIRE] = 2.0f * ci;
        outb[20 + WIRE] = zz;
    }
}

// ---------------------------------------------------------------------------
// prep kernel: pqc_params = emb @ W^T + b ; store cos/sin(theta/2)
// grid = 128 (one block per batch b), 256 threads
// ---------------------------------------------------------------------------
#define PREP_SMEM ((32 * 513 + 40 * 512) * 4)

__global__ void __launch_bounds__(256, 1)
prep_kernel(const float* __restrict__ emb, const float* __restrict__ W,
            const float* __restrict__ bias) {
    extern __shared__ float sm[];
    float* emb_s = sm;               // 32 x 513 (padded)
    float* W_s   = sm + 32 * 513;    // 40 x 512
    const int b = blockIdx.x, tid = threadIdx.x;

    for (int i = tid; i < 32 * 512; i += 256) {
        int l = i >> 9, d = i & 511;
        emb_s[l * 513 + d] = emb[(b * 32 + l) * 512 + d];
    }
    for (int i = tid; i < 40 * 512; i += 256) W_s[i] = W[i];
    __syncthreads();

    const int l  = tid & 31;
    const int kg = tid >> 5;             // 0..7, each handles 5 k's
    float acc[5] = {0.f, 0.f, 0.f, 0.f, 0.f};
    const float* er = emb_s + l * 513;
    const float* wr = W_s + kg * 5 * 512;
#pragma unroll 4
    for (int d = 0; d < 512; ++d) {
        float a = er[d];
#pragma unroll
        for (int j = 0; j < 5; ++j) acc[j] += wr[j * 512 + d] * a;
    }
#pragma unroll
    for (int j = 0; j < 5; ++j) {
        int k = kg * 5 + j;
        float th = 0.5f * (acc[j] + bias[k]);
        float sv, cv;
        __sincosf(th, &sv, &cv);
        int base = ((b * 32 + l) * 40 + k) * 2;
        g_cs[base]     = cv;
        g_cs[base + 1] = sv;
    }
}

// ---------------------------------------------------------------------------
// main kernel: one CTA per batch b, 512 threads (16 warps)
// ---------------------------------------------------------------------------
#define MAIN_SMEM ((2048 + 2048 + 16384 + 2560 + 64 + 80 + 16) * 4)

__global__ void __launch_bounds__(512, 1)
main_kernel(const float* __restrict__ lcu_re, const float* __restrict__ lcu_im,
            const float* __restrict__ qsvt, const float* __restrict__ ffp,
            float* __restrict__ out) {
    extern __shared__ float sm[];
    float2* cur   = (float2*)sm;                 // 1024
    float2* nxt   = cur + 1024;                  // 1024
    float2* red   = nxt + 1024;                  // 8 * 1024
    float*  cs_s  = (float*)(red + 8 * 1024);    // 32*40*2
    float2* lcu_s = (float2*)(cs_s + 2560);      // 32
    float*  ffcs  = (float*)(lcu_s + 32);        // 80
    float*  rsum  = ffcs + 80;                   // 16

    const int b = blockIdx.x;
    const int tid = threadIdx.x;
    const int w = tid >> 5;
    const unsigned lane = tid & 31u;

    // stage cos/sin table for this batch
    const float* gbase = g_cs + b * (NL * NPQ * 2);
    for (int i = tid; i < NL * NPQ * 2; i += 512) cs_s[i] = gbase[i];

    // ff gate trig
    if (tid < 40) {
        float sv, cv;
        __sincosf(0.5f * ffp[tid], &sv, &cv);
        ffcs[2 * tid] = cv;
        ffcs[2 * tid + 1] = sv;
    }

    // normalized lcu weights (warp 1)
    if (w == 1) {
        float re = lcu_re[lane], im = lcu_im[lane];
        float S = sqrtf(re * re + im * im);
#pragma unroll
        for (int m = 16; m; m >>= 1) S += __shfl_xor_sync(0xffffffffu, S, m);
        lcu_s[lane] = make_float2(re / S, im / S);
    }

    // init state |0>
    cur[tid] = make_float2(0.f, 0.f);
    cur[tid + 512] = make_float2(0.f, 0.f);
    if (tid == 0) cur[0] = make_float2(1.f, 0.f);

    const float q0 = qsvt[0], q1 = qsvt[1], q2 = qsvt[2];
    float2 acc0 = make_float2(tid == 0 ? q0 : 0.f, 0.f);
    float2 acc1 = make_float2(0.f, 0.f);
    __syncthreads();

    float2 s[32];

    for (int step = 1; step <= 2; ++step) {
        const float qk = (step == 1) ? q1 : q2;
        for (int pass = 0; pass < 2; ++pass) {
            const int l = w + pass * 16;
            // load full state into warp registers
#pragma unroll
            for (int r = 0; r < 32; ++r) s[r] = cur[r * 32 + lane];
            // apply 40 gates
            run_gates(s, cs_s + l * 80, lane);
            // scale by complex lcu weight
            const float2 lw = lcu_s[l];
#pragma unroll
            for (int r = 0; r < 32; ++r) {
                float2 v = s[r];
                s[r].x = lw.x * v.x - lw.y * v.y;
                s[r].y = lw.x * v.y + lw.y * v.x;
            }
            // tree-reduce 16 warps -> warp 0
#pragma unroll
            for (int h = 8; h >= 1; h >>= 1) {
                if (w >= h && w < 2 * h) {
#pragma unroll
                    for (int r = 0; r < 32; ++r) red[(w - h) * 1024 + r * 32 + lane] = s[r];
                }
                __syncthreads();
                if (w < h) {
#pragma unroll
                    for (int r = 0; r < 32; ++r) {
                        float2 t = red[w * 1024 + r * 32 + lane];
                        s[r].x += t.x; s[r].y += t.y;
                    }
                }
                __syncthreads();
            }
            if (w == 0) {
                if (pass == 0) {
#pragma unroll
                    for (int r = 0; r < 32; ++r) nxt[r * 32 + lane] = s[r];
                } else {
#pragma unroll
                    for (int r = 0; r < 32; ++r) {
                        float2 t = nxt[r * 32 + lane];
                        nxt[r * 32 + lane] = make_float2(t.x + s[r].x, t.y + s[r].y);
                    }
                }
            }
            __syncthreads();
        }
        // accumulate qsvt term, advance mono
        float2 n0 = nxt[tid], n1 = nxt[tid + 512];
        acc0.x += qk * n0.x; acc0.y += qk * n0.y;
        acc1.x += qk * n1.x; acc1.y += qk * n1.y;
        cur[tid] = n0; cur[tid + 512] = n1;
        __syncthreads();
    }

    // normalize acc
    float p = acc0.x * acc0.x + acc0.y * acc0.y + acc1.x * acc1.x + acc1.y * acc1.y;
#pragma unroll
    for (int m = 16; m; m >>= 1) p += __shfl_xor_sync(0xffffffffu, p, m);
    if (lane == 0) rsum[w] = p;
    __syncthreads();
    if (tid == 0) {
        float t = 0.f;
#pragma unroll
        for (int i = 0; i < 16; ++i) t += rsum[i];
        rsum[0] = rsqrtf(t);
    }
    __syncthreads();
    const float inv = rsum[0];
    cur[tid]       = make_float2(acc0.x * inv, acc0.y * inv);
    cur[tid + 512] = make_float2(acc1.x * inv, acc1.y * inv);
    __syncthreads();

    // feed-forward PQC (warp 0)
    if (w == 0) {
#pragma unroll
        for (int r = 0; r < 32; ++r) s[r] = cur[r * 32 + lane];
        run_gates(s, ffcs, lane);
#pragma unroll
        for (int r = 0; r < 32; ++r) cur[r * 32 + lane] = s[r];
    }
    __syncthreads();

    // measurement: warps 0..9, one wire each
    if (w < 10) {
#pragma unroll
        for (int r = 0; r < 32; ++r) s[r] = cur[r * 32 + lane];
        float* outb = out + b * 30;
        switch (w) {
            case 0: measure_wire<0>(s, lane, outb); break;
            case 1: measure_wire<1>(s, lane, outb); break;
            case 2: measure_wire<2>(s, lane, outb); break;
            case 3: measure_wire<3>(s, lane, outb); break;
            case 4: measure_wire<4>(s, lane, outb); break;
            case 5: measure_wire<5>(s, lane, outb); break;
            case 6: measure_wire<6>(s, lane, outb); break;
            case 7: measure_wire<7>(s, lane, outb); break;
            case 8: measure_wire<8>(s, lane, outb); break;
            case 9: measure_wire<9>(s, lane, outb); break;
        }
    }
}

// ---------------------------------------------------------------------------
extern "C" void kernel_launch(void* const* d_in, const int* in_sizes, int n_in,
                              void* d_out, int out_size) {
    const float* emb    = (const float*)d_in[0];
    const float* W      = (const float*)d_in[1];
    const float* bias   = (const float*)d_in[2];
    const float* lcu_re = (const float*)d_in[3];
    const float* lcu_im = (const float*)d_in[4];
    const float* qsvt   = (const float*)d_in[5];
    const float* ffp    = (const float*)d_in[6];
    float* out = (float*)d_out;

    cudaFuncSetAttribute(prep_kernel, cudaFuncAttributeMaxDynamicSharedMemorySize, PREP_SMEM);
    cudaFuncSetAttribute(main_kernel, cudaFuncAttributeMaxDynamicSharedMemorySize, MAIN_SMEM);

    prep_kernel<<<NB, 256, PREP_SMEM>>>(emb, W, bias);
    main_kernel<<<NB, 512, MAIN_SMEM>>>(lcu_re, lcu_im, qsvt, ffp, out);
}

// round 3
// speedup vs baseline: 1.0754x; 1.0754x over previous
#include <cuda_runtime.h>
#include <math.h>

#define NQBITS 10
#define SDIM   1024
#define NL     32
#define NB     128
#define NPQ    40

typedef unsigned long long u64;

// ---------------------------------------------------------------------------
// scratch: cos/sin of theta/2 per (b, l, gate)
// ---------------------------------------------------------------------------
__device__ float g_cs[NB * NL * NPQ * 2];

// ---------------------------------------------------------------------------
// gate tables (compile-time).  bit position = 9 - wire.
// type: 0 = RY (PA = bit pos), 1 = CRX (PA = control bit, PB = target bit)
// ---------------------------------------------------------------------------
constexpr int G_TYPE[40] = {0,0,0,0,0,0,0,0,0,0, 1,1,1,1,1,1,1,1,1,1,
                            0,0,0,0,0,0,0,0,0,0, 1,1,1,1,1,1,1,1,1,1};
constexpr int G_PA[40]   = {9,8,7,6,5,4,3,2,1,0, 0,1,2,3,4,5,6,7,8,9,
                            9,8,7,6,5,4,3,2,1,0, 0,9,8,7,6,5,4,3,2,1};
constexpr int G_PB[40]   = {0,0,0,0,0,0,0,0,0,0, 9,0,1,2,3,4,5,6,7,8,
                            0,0,0,0,0,0,0,0,0,0, 1,0,9,8,7,6,5,4,3,2};

// ---------------------------------------------------------------------------
// f32x2 helpers (packed 2xfp32 in a 64-bit register pair)
// ---------------------------------------------------------------------------
__device__ __forceinline__ u64 F2(float2 v) {
    u64 r; asm("mov.b64 %0, {%1,%2};" : "=l"(r) : "f"(v.x), "f"(v.y)); return r;
}
__device__ __forceinline__ float2 U2(u64 v) {
    float2 p; asm("mov.b64 {%0,%1}, %2;" : "=f"(p.x), "=f"(p.y) : "l"(v)); return p;
}
__device__ __forceinline__ u64 fma2(u64 a, u64 b, u64 c) {
    u64 d; asm("fma.rn.f32x2 %0, %1, %2, %3;" : "=l"(d) : "l"(a), "l"(b), "l"(c)); return d;
}
__device__ __forceinline__ u64 mul2(u64 a, u64 b) {
    u64 d; asm("mul.rn.f32x2 %0, %1, %2;" : "=l"(d) : "l"(a), "l"(b)); return d;
}
__device__ __forceinline__ u64 add2(u64 a, u64 b) {
    u64 d; asm("add.rn.f32x2 %0, %1, %2;" : "=l"(d) : "l"(a), "l"(b)); return d;
}
template<int M>
__device__ __forceinline__ u64 shfl2(u64 v) {
    float2 t = U2(v);
    t.x = __shfl_xor_sync(0xffffffffu, t.x, M);
    t.y = __shfl_xor_sync(0xffffffffu, t.y, M);
    return F2(t);
}
__device__ __forceinline__ u64 swap2(u64 v) {
    float2 t = U2(v);
    return F2(make_float2(t.y, t.x));
}

// ---------------------------------------------------------------------------
// state layout per warp: amp index = (v + 16*h)*32 + lane,  v in [0,16), h in {0,1}
//   X[v] packs (x_{h=0}, x_{h=1}),  Y[v] packs (y_{h=0}, y_{h=1})
//   bit P<5  -> lane bit,  5<=P<9 -> v bit (P-5),  P=9 -> packed half h
// ---------------------------------------------------------------------------

template<int P>
__device__ __forceinline__ void ry_gate(u64 (&X)[16], u64 (&Y)[16],
                                        float c, float s, unsigned lane) {
    if constexpr (P < 5) {
        const float sg = ((lane >> P) & 1u) ? s : -s;
        const u64 cc = F2(make_float2(c, c)), sg2 = F2(make_float2(sg, sg));
#pragma unroll
        for (int v = 0; v < 16; ++v) {
            X[v] = fma2(sg2, shfl2<(1 << P)>(X[v]), mul2(cc, X[v]));
            Y[v] = fma2(sg2, shfl2<(1 << P)>(Y[v]), mul2(cc, Y[v]));
        }
    } else if constexpr (P < 9) {
        constexpr int TB = 1 << (P - 5);
        const u64 cc = F2(make_float2(c, c));
        const u64 sp = F2(make_float2(s, s)), sn = F2(make_float2(-s, -s));
#pragma unroll
        for (int v0 = 0; v0 < 16; ++v0) {
            if (v0 & TB) continue;
            const int v1 = v0 | TB;
            u64 a0x = X[v0], a1x = X[v1], a0y = Y[v0], a1y = Y[v1];
            X[v0] = fma2(sn, a1x, mul2(cc, a0x));
            X[v1] = fma2(sp, a0x, mul2(cc, a1x));
            Y[v0] = fma2(sn, a1y, mul2(cc, a0y));
            Y[v1] = fma2(sp, a0y, mul2(cc, a1y));
        }
    } else {  // P == 9 : packed halves. lo' = c*lo - s*hi ; hi' = c*hi + s*lo
        const u64 cc = F2(make_float2(c, c)), sv = F2(make_float2(-s, s));
#pragma unroll
        for (int v = 0; v < 16; ++v) {
            X[v] = fma2(sv, swap2(X[v]), mul2(cc, X[v]));
            Y[v] = fma2(sv, swap2(Y[v]), mul2(cc, Y[v]));
        }
    }
}

// CRX: x' = ce*x + se*p_y ; y' = ce*y - se*p_x  (per active branch)
template<int A, int B>
__device__ __forceinline__ void crx_gate(u64 (&X)[16], u64 (&Y)[16],
                                         float c, float s, unsigned lane) {
    float2 cef, sef;
    if constexpr (A < 5) {              // lane-bit control: identity trick
        const int cb = (lane >> A) & 1u;
        const float ce = cb ? c : 1.0f, se = cb ? s : 0.0f;
        cef = make_float2(ce, ce); sef = make_float2(se, se);
    } else if constexpr (A == 9) {      // packed-half control: per-half coeffs
        cef = make_float2(1.0f, c); sef = make_float2(0.0f, s);
    } else {                            // v-bit control: restrict loop
        cef = make_float2(c, c); sef = make_float2(s, s);
    }
    const u64 ce2 = F2(cef), se2 = F2(sef);
    const u64 sn2 = F2(make_float2(-sef.x, -sef.y));
    constexpr bool vctrl = (A >= 5 && A < 9);
    constexpr int CB = vctrl ? (1 << (A - 5)) : 0;

    if constexpr (B < 5) {              // lane-bit target
#pragma unroll
        for (int v = 0; v < 16; ++v) {
            if (vctrl && !(v & CB)) continue;
            u64 px = shfl2<(1 << B)>(X[v]);
            u64 py = shfl2<(1 << B)>(Y[v]);
            X[v] = fma2(se2, py, mul2(ce2, X[v]));
            Y[v] = fma2(sn2, px, mul2(ce2, Y[v]));
        }
    } else if constexpr (B < 9) {       // v-bit target
        constexpr int TB = 1 << (B - 5);
#pragma unroll
        for (int v0 = 0; v0 < 16; ++v0) {
            if (v0 & TB) continue;
            if (vctrl && !(v0 & CB)) continue;
            const int v1 = v0 | TB;
            u64 a0x = X[v0], a0y = Y[v0], a1x = X[v1], a1y = Y[v1];
            X[v0] = fma2(se2, a1y, mul2(ce2, a0x));
            Y[v0] = fma2(sn2, a1x, mul2(ce2, a0y));
            X[v1] = fma2(se2, a0y, mul2(ce2, a1x));
            Y[v1] = fma2(sn2, a0x, mul2(ce2, a1y));
        }
    } else {                            // B == 9 : packed-half target
#pragma unroll
        for (int v = 0; v < 16; ++v) {
            if (vctrl && !(v & CB)) continue;
            u64 sx = swap2(X[v]), sy = swap2(Y[v]);
            X[v] = fma2(se2, sy, mul2(ce2, X[v]));
            Y[v] = fma2(sn2, sx, mul2(ce2, Y[v]));
        }
    }
}

template<int K>
__device__ __forceinline__ void do_gate(u64 (&X)[16], u64 (&Y)[16],
                                        const float* csl, unsigned lane) {
    const float c  = csl[2 * K];
    const float sn = csl[2 * K + 1];
    if constexpr (G_TYPE[K] == 0) ry_gate<G_PA[K]>(X, Y, c, sn, lane);
    else                          crx_gate<G_PA[K], G_PB[K]>(X, Y, c, sn, lane);
}

template<int K = 0>
__device__ __forceinline__ void run_gates(u64 (&X)[16], u64 (&Y)[16],
                                          const float* csl, unsigned lane) {
    if constexpr (K < 40) {
        do_gate<K>(X, Y, csl, lane);
        run_gates<K + 1>(X, Y, csl, lane);
    }
}

// ---- measurement of one wire (x, y, z) from float2 state s[r], amp=r*32+lane
template<int WIRE>
__device__ __forceinline__ void measure_wire(const float2 (&s)[32], unsigned lane, float* outb) {
    constexpr int P = 9 - WIRE;
    float cr = 0.f, ci = 0.f, zz = 0.f;
    if constexpr (P < 5) {
        const int bit = (lane >> P) & 1u;
        const float f0 = bit ? 0.f : 1.f;
        const float zs = bit ? -1.f : 1.f;
#pragma unroll
        for (int r = 0; r < 32; ++r) {
            float px = __shfl_xor_sync(0xffffffffu, s[r].x, 1 << P);
            float py = __shfl_xor_sync(0xffffffffu, s[r].y, 1 << P);
            cr += f0 * (s[r].x * px + s[r].y * py);
            ci += f0 * (s[r].x * py - s[r].y * px);
            zz += zs * (s[r].x * s[r].x + s[r].y * s[r].y);
        }
    } else {
        constexpr int RB = P - 5;
#pragma unroll
        for (int r0 = 0; r0 < 32; ++r0) {
            if ((r0 >> RB) & 1) continue;
            const int r1 = r0 | (1 << RB);
            float2 a0 = s[r0], a1 = s[r1];
            cr += a0.x * a1.x + a0.y * a1.y;
            ci += a0.x * a1.y - a0.y * a1.x;
            zz += (a0.x * a0.x + a0.y * a0.y) - (a1.x * a1.x + a1.y * a1.y);
        }
    }
#pragma unroll
    for (int m = 16; m; m >>= 1) {
        cr += __shfl_xor_sync(0xffffffffu, cr, m);
        ci += __shfl_xor_sync(0xffffffffu, ci, m);
        zz += __shfl_xor_sync(0xffffffffu, zz, m);
    }
    if (lane == 0) {
        outb[WIRE]      = 2.0f * cr;
        outb[10 + WIRE] = 2.0f * ci;
        outb[20 + WIRE] = zz;
    }
}

// ---------------------------------------------------------------------------
// prep kernel: pqc_params = emb @ W^T + b ; store cos/sin(theta/2)
// ---------------------------------------------------------------------------
#define PREP_SMEM ((32 * 513 + 40 * 512) * 4)

__global__ void __launch_bounds__(256, 1)
prep_kernel(const float* __restrict__ emb, const float* __restrict__ W,
            const float* __restrict__ bias) {
    extern __shared__ float sm[];
    float* emb_s = sm;               // 32 x 513 (padded)
    float* W_s   = sm + 32 * 513;    // 40 x 512
    const int b = blockIdx.x, tid = threadIdx.x;

    for (int i = tid; i < 32 * 512; i += 256) {
        int l = i >> 9, d = i & 511;
        emb_s[l * 513 + d] = emb[(b * 32 + l) * 512 + d];
    }
    for (int i = tid; i < 40 * 512; i += 256) W_s[i] = W[i];
    __syncthreads();

    const int l  = tid & 31;
    const int kg = tid >> 5;             // 0..7, each handles 5 k's
    float acc[5] = {0.f, 0.f, 0.f, 0.f, 0.f};
    const float* er = emb_s + l * 513;
    const float* wr = W_s + kg * 5 * 512;
#pragma unroll 4
    for (int d = 0; d < 512; ++d) {
        float a = er[d];
#pragma unroll
        for (int j = 0; j < 5; ++j) acc[j] += wr[j * 512 + d] * a;
    }
#pragma unroll
    for (int j = 0; j < 5; ++j) {
        int k = kg * 5 + j;
        float th = 0.5f * (acc[j] + bias[k]);
        float sv, cv;
        __sincosf(th, &sv, &cv);
        int base = ((b * 32 + l) * 40 + k) * 2;
        g_cs[base]     = cv;
        g_cs[base + 1] = sv;
    }
}

// ---------------------------------------------------------------------------
// main kernel: one CTA per batch b, 512 threads (16 warps)
// smem: red (16x1024 u64 = 128KB) | cur (1024 u64) | cs (2560 f) | ffcs | lcu | rsum
// ---------------------------------------------------------------------------
#define MAIN_SMEM (16 * 1024 * 8 + 1024 * 8 + 2560 * 4 + 80 * 4 + 32 * 8 + 64)

__global__ void __launch_bounds__(512, 1)
main_kernel(const float* __restrict__ lcu_re, const float* __restrict__ lcu_im,
            const float* __restrict__ qsvt, const float* __restrict__ ffp,
            float* __restrict__ out) {
    extern __shared__ char smraw[];
    u64*    red   = (u64*)smraw;                 // 16 * 1024
    u64*    cur   = red + 16 * 1024;             // 1024 (slot = comp*512 + v*32 + lane)
    float*  cs_s  = (float*)(cur + 1024);        // 32*40*2
    float*  ffcs  = cs_s + 2560;                 // 80
    float2* lcu_s = (float2*)(ffcs + 80);        // 32
    float*  rsum  = (float*)(lcu_s + 32);        // 16

    const int b = blockIdx.x;
    const int tid = threadIdx.x;
    const int w = tid >> 5;
    const unsigned lane = tid & 31u;

    // stage cos/sin table for this batch
    const float* gbase = g_cs + b * (NL * NPQ * 2);
    for (int i = tid; i < NL * NPQ * 2; i += 512) cs_s[i] = gbase[i];

    // ff gate trig
    if (tid < 40) {
        float sv, cv;
        __sincosf(0.5f * ffp[tid], &sv, &cv);
        ffcs[2 * tid] = cv;
        ffcs[2 * tid + 1] = sv;
    }

    // normalized lcu weights (warp 1)
    if (w == 1) {
        float re = lcu_re[lane], im = lcu_im[lane];
        float S = sqrtf(re * re + im * im);
#pragma unroll
        for (int m = 16; m; m >>= 1) S += __shfl_xor_sync(0xffffffffu, S, m);
        lcu_s[lane] = make_float2(re / S, im / S);
    }

    // init state |0> in packed-slot layout
    cur[tid] = 0ull;
    cur[tid + 512] = 0ull;
    if (tid == 0) cur[0] = F2(make_float2(1.f, 0.f));

    const float q0 = qsvt[0], q1 = qsvt[1], q2 = qsvt[2];
    u64 acc0 = (tid == 0) ? F2(make_float2(q0, 0.f)) : 0ull;
    u64 acc1 = 0ull;
    __syncthreads();

    u64 X[16], Y[16];

    for (int step = 1; step <= 2; ++step) {
        const float qk = (step == 1) ? q1 : q2;
        u64 m0 = 0ull, m1 = 0ull;
        for (int pass = 0; pass < 2; ++pass) {
            const int l = w + pass * 16;
            // load state
#pragma unroll
            for (int v = 0; v < 16; ++v) {
                X[v] = cur[v * 32 + lane];
                Y[v] = cur[512 + v * 32 + lane];
            }
            // 40 gates
            run_gates(X, Y, cs_s + l * 80, lane);
            // complex LCU scale
            const float2 lw = lcu_s[l];
            const u64 av = F2(make_float2(lw.x, lw.x));
            const u64 bp = F2(make_float2(lw.y, lw.y));
            const u64 bn = F2(make_float2(-lw.y, -lw.y));
#pragma unroll
            for (int v = 0; v < 16; ++v) {
                u64 tx = X[v];
                X[v] = fma2(bn, Y[v], mul2(av, tx));
                Y[v] = fma2(bp, tx, mul2(av, Y[v]));
            }
            // stage to red
            u64* rw = red + w * 1024;
#pragma unroll
            for (int v = 0; v < 16; ++v) {
                rw[v * 32 + lane]       = X[v];
                rw[512 + v * 32 + lane] = Y[v];
            }
            __syncthreads();
            // flat 16-way sum: thread owns slots tid and tid+512
            u64 a0 = red[tid], a1 = red[tid + 512];
#pragma unroll
            for (int wi = 1; wi < 16; ++wi) {
                a0 = add2(a0, red[wi * 1024 + tid]);
                a1 = add2(a1, red[wi * 1024 + tid + 512]);
            }
            m0 = (pass == 0) ? a0 : add2(m0, a0);
            m1 = (pass == 0) ? a1 : add2(m1, a1);
            __syncthreads();   // red reuse / cur stability
        }
        const u64 qk2 = F2(make_float2(qk, qk));
        acc0 = fma2(qk2, m0, acc0);
        acc1 = fma2(qk2, m1, acc1);
        cur[tid] = m0;
        cur[tid + 512] = m1;
        __syncthreads();
    }

    // normalize acc
    {
        float2 t0 = U2(acc0), t1 = U2(acc1);
        float p = t0.x * t0.x + t0.y * t0.y + t1.x * t1.x + t1.y * t1.y;
#pragma unroll
        for (int m = 16; m; m >>= 1) p += __shfl_xor_sync(0xffffffffu, p, m);
        if (lane == 0) rsum[w] = p;
    }
    __syncthreads();
    if (tid == 0) {
        float t = 0.f;
#pragma unroll
        for (int i = 0; i < 16; ++i) t += rsum[i];
        rsum[0] = rsqrtf(t);
    }
    __syncthreads();
    {
        const float inv = rsum[0];
        const u64 iv = F2(make_float2(inv, inv));
        cur[tid]       = mul2(acc0, iv);
        cur[tid + 512] = mul2(acc1, iv);
    }
    __syncthreads();

    // feed-forward PQC (warp 0), then unpack to plain float2 layout for measure
    float2* fin = (float2*)red;
    if (w == 0) {
#pragma unroll
        for (int v = 0; v < 16; ++v) {
            X[v] = cur[v * 32 + lane];
            Y[v] = cur[512 + v * 32 + lane];
        }
        run_gates(X, Y, ffcs, lane);
#pragma unroll
        for (int v = 0; v < 16; ++v) {
            float2 xv = U2(X[v]), yv = U2(Y[v]);
            fin[v * 32 + lane]        = make_float2(xv.x, yv.x);
            fin[(v + 16) * 32 + lane] = make_float2(xv.y, yv.y);
        }
    }
    __syncthreads();

    // measurement: warps 0..9, one wire each
    if (w < 10) {
        float2 s[32];
#pragma unroll
        for (int r = 0; r < 32; ++r) s[r] = fin[r * 32 + lane];
        float* outb = out + b * 30;
        switch (w) {
            case 0: measure_wire<0>(s, lane, outb); break;
            case 1: measure_wire<1>(s, lane, outb); break;
            case 2: measure_wire<2>(s, lane, outb); break;
            case 3: measure_wire<3>(s, lane, outb); break;
            case 4: measure_wire<4>(s, lane, outb); break;
            case 5: measure_wire<5>(s, lane, outb); break;
            case 6: measure_wire<6>(s, lane, outb); break;
            case 7: measure_wire<7>(s, lane, outb); break;
            case 8: measure_wire<8>(s, lane, outb); break;
            case 9: measure_wire<9>(s, lane, outb); break;
        }
    }
}

// ---------------------------------------------------------------------------
extern "C" void kernel_launch(void* const* d_in, const int* in_sizes, int n_in,
                              void* d_out, int out_size) {
    const float* emb    = (const float*)d_in[0];
    const float* W      = (const float*)d_in[1];
    const float* bias   = (const float*)d_in[2];
    const float* lcu_re = (const float*)d_in[3];
    const float* lcu_im = (const float*)d_in[4];
    const float* qsvt   = (const float*)d_in[5];
    const float* ffp    = (const float*)d_in[6];
    float* out = (float*)d_out;

    cudaFuncSetAttribute(prep_kernel, cudaFuncAttributeMaxDynamicSharedMemorySize, PREP_SMEM);
    cudaFuncSetAttribute(main_kernel, cudaFuncAttributeMaxDynamicSharedMemorySize, MAIN_SMEM);

    prep_kernel<<<NB, 256, PREP_SMEM>>>(emb, W, bias);
    main_kernel<<<NB, 512, MAIN_SMEM>>>(lcu_re, lcu_im, qsvt, ffp, out);
}